// round 2
// baseline (speedup 1.0000x reference)
#include <cuda_runtime.h>

#define NCLS 19
#define HW_   (512*1024)        // 2^19
#define NPIX  (4*HW_)           // 2,097,152
#define NPIX4 (NPIX/4)
#define GRIDB 1184
#define TB    256

// ---- static scratch (no allocations allowed) ----
__device__ float    g_loss[NPIX];        // 8 MB
__device__ unsigned g_hist0[4096];
__device__ unsigned g_hist1[4096];
__device__ unsigned g_cnt2[256];
__device__ double   g_sum2[256];
__device__ double   g_sumHi;             // sum of losses strictly above level-1 bin
__device__ unsigned g_cntHi;
__device__ double   g_sumAll;            // fallback: mean over everything
__device__ unsigned g_prefix0, g_prefix01, g_k1, g_k2;
__device__ unsigned g_done0, g_done1, g_done2;
__device__ int      g_tmode;             // 1 = int64 targets, 0 = int32

// ------------------------------------------------------------------
__global__ void k_init(const void* tgt_raw) {
    int t = blockIdx.x * blockDim.x + threadIdx.x;
    if (t < 4096) { g_hist0[t] = 0; g_hist1[t] = 0; }
    if (t < 256)  { g_cnt2[t] = 0; g_sum2[t] = 0.0; }
    if (t == 0) {
        g_prefix0 = 0xFFFFFFFFu; g_prefix01 = 0xFFFFFFFFu;
        g_k1 = 0; g_k2 = 0;
        g_sumHi = 0.0; g_cntHi = 0; g_sumAll = 0.0;
        g_done0 = 0; g_done1 = 0; g_done2 = 0;
        const long long* t64 = (const long long*)tgt_raw;
        int is64 = 1;
        #pragma unroll
        for (int i = 0; i < 8; i++) {
            long long v = t64[i];
            if (v < 0 || v >= (long long)NCLS) is64 = 0;
        }
        g_tmode = is64;
    }
}

// ------------------------------------------------------------------
// Pass A: fused NLL (no-max logsumexp) + level-0 histogram + fused scan0
__global__ void k_loss(const float* __restrict__ logits, const void* __restrict__ tgt_raw) {
    __shared__ unsigned sh[4096];
    for (int i = threadIdx.x; i < 4096; i += TB) sh[i] = 0;
    __syncthreads();

    const int tmode = g_tmode;
    const long long* t64 = (const long long*)tgt_raw;
    const int4*      t32 = (const int4*)tgt_raw;

    int stride = gridDim.x * blockDim.x;
    for (int q = blockIdx.x * blockDim.x + threadIdx.x; q < NPIX4; q += stride) {
        int p  = q << 2;
        int n  = p >> 19;
        int hw = p & (HW_ - 1);
        const float4* base = (const float4*)(logits + (size_t)n * (NCLS * (size_t)HW_) + hw);
        int t0, t1, t2, t3;
        if (tmode) {
            t0 = (int)t64[p]; t1 = (int)t64[p + 1]; t2 = (int)t64[p + 2]; t3 = (int)t64[p + 3];
        } else {
            int4 tt = __ldg(t32 + q);
            t0 = tt.x; t1 = tt.y; t2 = tt.z; t3 = tt.w;
        }
        float s0 = 0.f, s1 = 0.f, s2 = 0.f, s3 = 0.f;
        float x0 = 0.f, x1 = 0.f, x2 = 0.f, x3 = 0.f;
        #pragma unroll
        for (int c = 0; c < NCLS; c++) {
            float4 v = __ldg(base + (size_t)c * (HW_ / 4));
            s0 += __expf(v.x); s1 += __expf(v.y); s2 += __expf(v.z); s3 += __expf(v.w);
            if (c == t0) x0 = v.x;
            if (c == t1) x1 = v.y;
            if (c == t2) x2 = v.z;
            if (c == t3) x3 = v.w;
        }
        float l0 = __logf(s0) - x0, l1 = __logf(s1) - x1;
        float l2 = __logf(s2) - x2, l3 = __logf(s3) - x3;
        ((float4*)g_loss)[q] = make_float4(l0, l1, l2, l3);
        if (l0 > 0.f) atomicAdd(&sh[__float_as_uint(l0) >> 20], 1u);
        if (l1 > 0.f) atomicAdd(&sh[__float_as_uint(l1) >> 20], 1u);
        if (l2 > 0.f) atomicAdd(&sh[__float_as_uint(l2) >> 20], 1u);
        if (l3 > 0.f) atomicAdd(&sh[__float_as_uint(l3) >> 20], 1u);
    }
    __syncthreads();
    for (int i = threadIdx.x; i < 4096; i += TB) {
        unsigned c = sh[i];
        if (c) atomicAdd(&g_hist0[i], c);
    }
    __threadfence();
    __syncthreads();
    __shared__ bool lastb;
    if (threadIdx.x == 0) lastb = (atomicAdd(&g_done0, 1u) == gridDim.x - 1);
    __syncthreads();
    if (!lastb) return;

    // ---- fused scan0 (256 threads, 16 descending bins each) ----
    int t = threadIdx.x;
    unsigned cnt[16]; unsigned myv = 0;
    #pragma unroll
    for (int i = 0; i < 16; i++) { cnt[i] = __ldcg(&g_hist0[4095 - (t * 16 + i)]); myv += cnt[i]; }
    __shared__ unsigned ss[256];
    ss[t] = myv; __syncthreads();
    for (int off = 1; off < 256; off <<= 1) {
        unsigned x = (t >= off) ? ss[t - off] : 0u;
        __syncthreads(); ss[t] += x; __syncthreads();
    }
    unsigned total = ss[255];
    if (total == 0) return;                      // prefixes stay invalid
    unsigned nk = (unsigned)(0.7f * (float)total);
    if (nk < 100000u) nk = 100000u;
    if (nk > total)   nk = total;
    unsigned hi = ss[t], lo = hi - myv;
    if (nk > lo && nk <= hi) {
        unsigned cum = lo;
        #pragma unroll
        for (int i = 0; i < 16; i++) {
            cum += cnt[i];
            if (nk <= cum) { g_prefix0 = 4095u - (t * 16 + i); g_k1 = nk - (cum - cnt[i]); break; }
        }
    }
}

// ------------------------------------------------------------------
// Pass B: level-1 histogram (bits[19:8] within prefix0 bin) + fused scan1
__global__ void k_hist1() {
    __shared__ unsigned sh[4096];
    for (int i = threadIdx.x; i < 4096; i += TB) sh[i] = 0;
    __syncthreads();
    unsigned pref = g_prefix0;
    const uint4* lossv = (const uint4*)g_loss;
    int stride = gridDim.x * blockDim.x;
    for (int q = blockIdx.x * blockDim.x + threadIdx.x; q < NPIX4; q += stride) {
        uint4 b = __ldg(lossv + q);
        if ((int)b.x > 0 && (b.x >> 20) == pref) atomicAdd(&sh[(b.x >> 8) & 0xFFFu], 1u);
        if ((int)b.y > 0 && (b.y >> 20) == pref) atomicAdd(&sh[(b.y >> 8) & 0xFFFu], 1u);
        if ((int)b.z > 0 && (b.z >> 20) == pref) atomicAdd(&sh[(b.z >> 8) & 0xFFFu], 1u);
        if ((int)b.w > 0 && (b.w >> 20) == pref) atomicAdd(&sh[(b.w >> 8) & 0xFFFu], 1u);
    }
    __syncthreads();
    for (int i = threadIdx.x; i < 4096; i += TB) {
        unsigned c = sh[i];
        if (c) atomicAdd(&g_hist1[i], c);
    }
    __threadfence();
    __syncthreads();
    __shared__ bool lastb;
    if (threadIdx.x == 0) lastb = (atomicAdd(&g_done1, 1u) == gridDim.x - 1);
    __syncthreads();
    if (!lastb) return;
    if (pref == 0xFFFFFFFFu) return;

    int t = threadIdx.x;
    unsigned cnt[16]; unsigned myv = 0;
    #pragma unroll
    for (int i = 0; i < 16; i++) { cnt[i] = __ldcg(&g_hist1[4095 - (t * 16 + i)]); myv += cnt[i]; }
    __shared__ unsigned ss[256];
    ss[t] = myv; __syncthreads();
    for (int off = 1; off < 256; off <<= 1) {
        unsigned x = (t >= off) ? ss[t - off] : 0u;
        __syncthreads(); ss[t] += x; __syncthreads();
    }
    unsigned k = g_k1;
    unsigned hi = ss[t], lo = hi - myv;
    if (k > lo && k <= hi) {
        unsigned cum = lo;
        #pragma unroll
        for (int i = 0; i < 16; i++) {
            cum += cnt[i];
            if (k <= cum) {
                unsigned bin = 4095u - (t * 16 + i);
                g_prefix01 = (pref << 12) | bin;
                g_k2 = k - (cum - cnt[i]);
                break;
            }
        }
    }
}

// ------------------------------------------------------------------
// Pass C: level-2 histogram with per-byte SUMS + sum/count above the bin,
// then fused threshold scan + final mean. No 4th pass needed.
__global__ void k_hist2_final(float* __restrict__ out) {
    __shared__ unsigned s_cnt2[256];
    __shared__ double   s_sum2[256];
    __shared__ double   s_sHi, s_sAll;
    __shared__ unsigned s_cHi;
    for (int i = threadIdx.x; i < 256; i += TB) { s_cnt2[i] = 0; s_sum2[i] = 0.0; }
    if (threadIdx.x == 0) { s_sHi = 0.0; s_sAll = 0.0; s_cHi = 0; }
    __syncthreads();

    unsigned pref = g_prefix01;
    const uint4* lossv = (const uint4*)g_loss;
    double sHi = 0.0, sAll = 0.0; unsigned cHi = 0;
    int stride = gridDim.x * blockDim.x;
    for (int q = blockIdx.x * blockDim.x + threadIdx.x; q < NPIX4; q += stride) {
        uint4 b = __ldg(lossv + q);
        #pragma unroll
        for (int j = 0; j < 4; j++) {
            unsigned bb = (j == 0) ? b.x : (j == 1) ? b.y : (j == 2) ? b.z : b.w;
            float l = __uint_as_float(bb);
            sAll += (double)l;
            if ((int)bb > 0) {
                unsigned p8 = bb >> 8;
                if (p8 == pref) {
                    atomicAdd(&s_cnt2[bb & 0xFFu], 1u);
                    atomicAdd(&s_sum2[bb & 0xFFu], (double)l);
                } else if (p8 > pref && pref != 0xFFFFFFFFu) {
                    sHi += (double)l; cHi++;
                }
            }
        }
    }
    atomicAdd(&s_sHi, sHi);
    atomicAdd(&s_sAll, sAll);
    atomicAdd(&s_cHi, cHi);
    __syncthreads();
    for (int i = threadIdx.x; i < 256; i += TB) {
        if (s_cnt2[i]) { atomicAdd(&g_cnt2[i], s_cnt2[i]); atomicAdd(&g_sum2[i], s_sum2[i]); }
    }
    if (threadIdx.x == 0) {
        if (s_cHi) { atomicAdd(&g_cntHi, s_cHi); atomicAdd(&g_sumHi, s_sHi); }
        atomicAdd(&g_sumAll, s_sAll);
    }
    __threadfence();
    __syncthreads();
    __shared__ bool lastb;
    if (threadIdx.x == 0) lastb = (atomicAdd(&g_done2, 1u) == gridDim.x - 1);
    __syncthreads();
    if (!lastb) return;

    if (threadIdx.x == 0) {
        double outv;
        if (pref == 0xFFFFFFFFu) {
            outv = __ldcg(&g_sumAll) / (double)NPIX;     // no valid pixels: plain mean
        } else {
            unsigned k2 = g_k2;
            unsigned cum = 0, scnt = 0;
            double ssum = 0.0;
            for (int b = 255; b >= 0; b--) {
                unsigned c = __ldcg(&g_cnt2[b]);
                ssum += __ldcg(&g_sum2[b]);
                scnt += c;
                cum  += c;
                if (cum >= k2) break;                     // threshold byte reached (ties kept)
            }
            double   ktot = __ldcg(&g_sumHi) + ssum;
            unsigned kcnt = __ldcg(&g_cntHi) + scnt;
            if (kcnt == 0) kcnt = 1;
            outv = ktot / (double)kcnt;
        }
        out[0] = (float)outv;
    }
}

// ------------------------------------------------------------------
extern "C" void kernel_launch(void* const* d_in, const int* in_sizes, int n_in,
                              void* d_out, int out_size) {
    const float* logits = (const float*)d_in[0];
    const void*  tgt    = d_in[1];
    float* out = (float*)d_out;

    k_init        <<<16, 256>>>(tgt);
    k_loss        <<<GRIDB, TB>>>(logits, tgt);
    k_hist1       <<<GRIDB, TB>>>();
    k_hist2_final <<<GRIDB, TB>>>(out);
}

// round 3
// speedup vs baseline: 1.5234x; 1.5234x over previous
#include <cuda_runtime.h>

#define NCLS 19
#define HW_   (512*1024)        // 2^19
#define NPIX  (4*HW_)           // 2,097,152
#define NPIX4 (NPIX/4)
#define GRIDB 1184
#define TB    256

// ---- static scratch (no allocations allowed) ----
__device__ float    g_loss[NPIX];        // 8 MB
__device__ unsigned g_hist0[4096];
__device__ unsigned g_hist1[4096];
__device__ unsigned g_cnt2[256];
__device__ float    g_sum2[256];
__device__ double   g_sumHi;             // sum of losses strictly above level-1 bin
__device__ unsigned g_cntHi;
__device__ double   g_sumAll;            // fallback only (no valid pixels)
__device__ unsigned g_prefix0, g_prefix01, g_k1, g_k2;
__device__ unsigned g_done0, g_done1, g_done2;
__device__ int      g_tmode;             // 1 = int64 targets, 0 = int32

// ------------------------------------------------------------------
__global__ void k_init(const void* tgt_raw) {
    int t = blockIdx.x * blockDim.x + threadIdx.x;
    if (t < 4096) { g_hist0[t] = 0; g_hist1[t] = 0; }
    if (t < 256)  { g_cnt2[t] = 0; g_sum2[t] = 0.f; }
    if (t == 0) {
        g_prefix0 = 0xFFFFFFFFu; g_prefix01 = 0xFFFFFFFFu;
        g_k1 = 0; g_k2 = 0;
        g_sumHi = 0.0; g_cntHi = 0; g_sumAll = 0.0;
        g_done0 = 0; g_done1 = 0; g_done2 = 0;
        const long long* t64 = (const long long*)tgt_raw;
        int is64 = 1;
        #pragma unroll
        for (int i = 0; i < 8; i++) {
            long long v = t64[i];
            if (v < 0 || v >= (long long)NCLS) is64 = 0;
        }
        g_tmode = is64;
    }
}

// ------------------------------------------------------------------
// Pass A: fused NLL (no-max logsumexp) + level-0 histogram + fused scan0
__global__ void k_loss(const float* __restrict__ logits, const void* __restrict__ tgt_raw) {
    __shared__ unsigned sh[4096];
    for (int i = threadIdx.x; i < 4096; i += TB) sh[i] = 0;
    __syncthreads();

    const int tmode = g_tmode;
    const longlong2* t64 = (const longlong2*)tgt_raw;
    const int4*      t32 = (const int4*)tgt_raw;

    int stride = gridDim.x * blockDim.x;
    for (int q = blockIdx.x * blockDim.x + threadIdx.x; q < NPIX4; q += stride) {
        int p  = q << 2;
        int n  = p >> 19;
        int hw = p & (HW_ - 1);
        const float4* base = (const float4*)(logits + (size_t)n * (NCLS * (size_t)HW_) + hw);
        int t0, t1, t2, t3;
        if (tmode) {
            longlong2 ta = __ldg(t64 + 2 * q);
            longlong2 tb = __ldg(t64 + 2 * q + 1);
            t0 = (int)ta.x; t1 = (int)ta.y; t2 = (int)tb.x; t3 = (int)tb.y;
        } else {
            int4 tt = __ldg(t32 + q);
            t0 = tt.x; t1 = tt.y; t2 = tt.z; t3 = tt.w;
        }
        float s0 = 0.f, s1 = 0.f, s2 = 0.f, s3 = 0.f;
        float x0 = 0.f, x1 = 0.f, x2 = 0.f, x3 = 0.f;
        #pragma unroll
        for (int c = 0; c < NCLS; c++) {
            float4 v = __ldg(base + (size_t)c * (HW_ / 4));
            s0 += __expf(v.x); s1 += __expf(v.y); s2 += __expf(v.z); s3 += __expf(v.w);
            if (c == t0) x0 = v.x;
            if (c == t1) x1 = v.y;
            if (c == t2) x2 = v.z;
            if (c == t3) x3 = v.w;
        }
        float l0 = __logf(s0) - x0, l1 = __logf(s1) - x1;
        float l2 = __logf(s2) - x2, l3 = __logf(s3) - x3;
        ((float4*)g_loss)[q] = make_float4(l0, l1, l2, l3);
        if (l0 > 0.f) atomicAdd(&sh[__float_as_uint(l0) >> 20], 1u);
        if (l1 > 0.f) atomicAdd(&sh[__float_as_uint(l1) >> 20], 1u);
        if (l2 > 0.f) atomicAdd(&sh[__float_as_uint(l2) >> 20], 1u);
        if (l3 > 0.f) atomicAdd(&sh[__float_as_uint(l3) >> 20], 1u);
    }
    __syncthreads();
    for (int i = threadIdx.x; i < 4096; i += TB) {
        unsigned c = sh[i];
        if (c) atomicAdd(&g_hist0[i], c);
    }
    __threadfence();
    __syncthreads();
    __shared__ bool lastb;
    if (threadIdx.x == 0) lastb = (atomicAdd(&g_done0, 1u) == gridDim.x - 1);
    __syncthreads();
    if (!lastb) return;

    // ---- fused scan0 (256 threads, 16 descending bins each) ----
    int t = threadIdx.x;
    unsigned cnt[16]; unsigned myv = 0;
    #pragma unroll
    for (int i = 0; i < 16; i++) { cnt[i] = __ldcg(&g_hist0[4095 - (t * 16 + i)]); myv += cnt[i]; }
    __shared__ unsigned ss[256];
    ss[t] = myv; __syncthreads();
    for (int off = 1; off < 256; off <<= 1) {
        unsigned x = (t >= off) ? ss[t - off] : 0u;
        __syncthreads(); ss[t] += x; __syncthreads();
    }
    unsigned total = ss[255];
    if (total == 0) return;                      // prefixes stay invalid
    unsigned nk = (unsigned)(0.7f * (float)total);
    if (nk < 100000u) nk = 100000u;
    if (nk > total)   nk = total;
    unsigned hi = ss[t], lo = hi - myv;
    if (nk > lo && nk <= hi) {
        unsigned cum = lo;
        #pragma unroll
        for (int i = 0; i < 16; i++) {
            cum += cnt[i];
            if (nk <= cum) { g_prefix0 = 4095u - (t * 16 + i); g_k1 = nk - (cum - cnt[i]); break; }
        }
    }
}

// ------------------------------------------------------------------
// Pass B: level-1 histogram (bits[19:8] within prefix0 bin) + fused scan1
__global__ void k_hist1() {
    __shared__ unsigned sh[4096];
    for (int i = threadIdx.x; i < 4096; i += TB) sh[i] = 0;
    __syncthreads();
    unsigned pref = g_prefix0;
    const uint4* lossv = (const uint4*)g_loss;
    int stride = gridDim.x * blockDim.x;
    for (int q = blockIdx.x * blockDim.x + threadIdx.x; q < NPIX4; q += stride) {
        uint4 b = __ldg(lossv + q);
        if ((int)b.x > 0 && (b.x >> 20) == pref) atomicAdd(&sh[(b.x >> 8) & 0xFFFu], 1u);
        if ((int)b.y > 0 && (b.y >> 20) == pref) atomicAdd(&sh[(b.y >> 8) & 0xFFFu], 1u);
        if ((int)b.z > 0 && (b.z >> 20) == pref) atomicAdd(&sh[(b.z >> 8) & 0xFFFu], 1u);
        if ((int)b.w > 0 && (b.w >> 20) == pref) atomicAdd(&sh[(b.w >> 8) & 0xFFFu], 1u);
    }
    __syncthreads();
    for (int i = threadIdx.x; i < 4096; i += TB) {
        unsigned c = sh[i];
        if (c) atomicAdd(&g_hist1[i], c);
    }
    __threadfence();
    __syncthreads();
    __shared__ bool lastb;
    if (threadIdx.x == 0) lastb = (atomicAdd(&g_done1, 1u) == gridDim.x - 1);
    __syncthreads();
    if (!lastb) return;
    if (pref == 0xFFFFFFFFu) return;

    int t = threadIdx.x;
    unsigned cnt[16]; unsigned myv = 0;
    #pragma unroll
    for (int i = 0; i < 16; i++) { cnt[i] = __ldcg(&g_hist1[4095 - (t * 16 + i)]); myv += cnt[i]; }
    __shared__ unsigned ss[256];
    ss[t] = myv; __syncthreads();
    for (int off = 1; off < 256; off <<= 1) {
        unsigned x = (t >= off) ? ss[t - off] : 0u;
        __syncthreads(); ss[t] += x; __syncthreads();
    }
    unsigned k = g_k1;
    unsigned hi = ss[t], lo = hi - myv;
    if (k > lo && k <= hi) {
        unsigned cum = lo;
        #pragma unroll
        for (int i = 0; i < 16; i++) {
            cum += cnt[i];
            if (k <= cum) {
                unsigned bin = 4095u - (t * 16 + i);
                g_prefix01 = (pref << 12) | bin;
                g_k2 = k - (cum - cnt[i]);
                break;
            }
        }
    }
}

// ------------------------------------------------------------------
// Pass C: level-2 per-byte cnt/sum + sum/count above the bin (register
// accumulators + shared TREE reduction, no hot-path doubles/contended
// atomics), then fused threshold scan + final mean.
__global__ void k_hist2_final(float* __restrict__ out) {
    __shared__ unsigned s_cnt2[256];
    __shared__ float    s_sum2[256];
    __shared__ double   s_rd[256];
    __shared__ unsigned s_rc[256];
    for (int i = threadIdx.x; i < 256; i += TB) { s_cnt2[i] = 0; s_sum2[i] = 0.f; }
    __syncthreads();

    unsigned pref = g_prefix01;
    const uint4* lossv = (const uint4*)g_loss;
    double sHi = 0.0;
    unsigned cHi = 0;
    int stride = gridDim.x * blockDim.x;

    if (pref != 0xFFFFFFFFu) {
        for (int q = blockIdx.x * blockDim.x + threadIdx.x; q < NPIX4; q += stride) {
            uint4 b = __ldg(lossv + q);
            #pragma unroll
            for (int j = 0; j < 4; j++) {
                unsigned bb = (j == 0) ? b.x : (j == 1) ? b.y : (j == 2) ? b.z : b.w;
                if ((int)bb > 0) {
                    unsigned p8 = bb >> 8;
                    if (p8 > pref) {
                        sHi += (double)__uint_as_float(bb); cHi++;
                    } else if (p8 == pref) {
                        atomicAdd(&s_cnt2[bb & 0xFFu], 1u);
                        atomicAdd(&s_sum2[bb & 0xFFu], __uint_as_float(bb));
                    }
                }
            }
        }
    } else {
        // no valid pixels: plain mean over everything
        for (int q = blockIdx.x * blockDim.x + threadIdx.x; q < NPIX4; q += stride) {
            uint4 b = __ldg(lossv + q);
            sHi += (double)__uint_as_float(b.x) + (double)__uint_as_float(b.y)
                 + (double)__uint_as_float(b.z) + (double)__uint_as_float(b.w);
        }
    }

    // block tree reduction of (sHi, cHi)
    int t = threadIdx.x;
    s_rd[t] = sHi; s_rc[t] = cHi;
    __syncthreads();
    for (int off = 128; off > 0; off >>= 1) {
        if (t < off) { s_rd[t] += s_rd[t + off]; s_rc[t] += s_rc[t + off]; }
        __syncthreads();
    }
    if (t == 0) {
        if (pref != 0xFFFFFFFFu) {
            atomicAdd(&g_sumHi, s_rd[0]);
            if (s_rc[0]) atomicAdd(&g_cntHi, s_rc[0]);
        } else {
            atomicAdd(&g_sumAll, s_rd[0]);
        }
    }
    for (int i = t; i < 256; i += TB) {
        if (s_cnt2[i]) { atomicAdd(&g_cnt2[i], s_cnt2[i]); atomicAdd(&g_sum2[i], s_sum2[i]); }
    }
    __threadfence();
    __syncthreads();
    __shared__ bool lastb;
    if (t == 0) lastb = (atomicAdd(&g_done2, 1u) == gridDim.x - 1);
    __syncthreads();
    if (!lastb) return;

    if (t == 0) {
        double outv;
        if (pref == 0xFFFFFFFFu) {
            outv = __ldcg(&g_sumAll) / (double)NPIX;
        } else {
            unsigned k2 = g_k2;
            unsigned cum = 0;
            double ssum = 0.0;
            for (int b = 255; b >= 0; b--) {
                unsigned c = __ldcg(&g_cnt2[b]);
                ssum += (double)__ldcg(&g_sum2[b]);
                cum  += c;
                if (cum >= k2) break;                 // threshold byte reached (ties kept)
            }
            double   ktot = __ldcg(&g_sumHi) + ssum;
            unsigned kcnt = __ldcg(&g_cntHi) + cum;
            if (kcnt == 0) kcnt = 1;
            outv = ktot / (double)kcnt;
        }
        out[0] = (float)outv;
    }
}

// ------------------------------------------------------------------
extern "C" void kernel_launch(void* const* d_in, const int* in_sizes, int n_in,
                              void* d_out, int out_size) {
    const float* logits = (const float*)d_in[0];
    const void*  tgt    = d_in[1];
    float* out = (float*)d_out;

    k_init        <<<16, 256>>>(tgt);
    k_loss        <<<GRIDB, TB>>>(logits, tgt);
    k_hist1       <<<GRIDB, TB>>>();
    k_hist2_final <<<GRIDB, TB>>>(out);
}

// round 5
// speedup vs baseline: 1.6403x; 1.0768x over previous
#include <cuda_runtime.h>

#define NCLS 19
#define HW_   (512*1024)        // 2^19
#define NPIX  (4*HW_)           // 2,097,152
#define NPIX4 (NPIX/4)
#define GRID_A 1024             // 1024*256 threads * 2 quads = NPIX4 exactly
#define GRID_B 592              // 4 CTAs/SM * 148 SMs
#define TB     256
#define VPT    4                // uint4 per thread in k_select (592*256*4 >= NPIX4)
#define INV    0xFFFFFFFFu

// ---- static scratch ----
__device__ float    g_loss[NPIX];
__device__ unsigned g_hist0[4096];
__device__ unsigned g_hist1[4096];
__device__ unsigned g_cnt2[256];
__device__ float    g_sum2[256];
__device__ double   g_sumHi;
__device__ unsigned g_cntHi;
__device__ unsigned g_prefix0, g_prefix01, g_k1, g_k2;
__device__ unsigned g_flag0, g_flag1, g_done1, g_done2;
__device__ int      g_tmode;

// ------------------------------------------------------------------
__global__ void k_init(const void* tgt_raw) {
    int t = blockIdx.x * blockDim.x + threadIdx.x;
    if (t < 4096) { g_hist0[t] = 0; g_hist1[t] = 0; }
    if (t < 256)  { g_cnt2[t] = 0; g_sum2[t] = 0.f; }
    if (t == 0) {
        g_prefix0 = INV; g_prefix01 = INV; g_k1 = 0; g_k2 = 0;
        g_sumHi = 0.0; g_cntHi = 0;
        g_flag0 = 0; g_flag1 = 0; g_done1 = 0; g_done2 = 0;
        const long long* t64 = (const long long*)tgt_raw;
        int is64 = 1;
        #pragma unroll
        for (int i = 0; i < 8; i++) {
            long long v = t64[i];
            if (v < 0 || v >= (long long)NCLS) is64 = 0;
        }
        g_tmode = is64;
    }
}

// ------------------------------------------------------------------
// Pass A: fused NLL (no-max logsumexp) + level-0 12-bit histogram
__global__ void __launch_bounds__(TB) k_loss(const float* __restrict__ logits,
                                             const void* __restrict__ tgt_raw) {
    __shared__ unsigned sh[4096];
    for (int i = threadIdx.x; i < 4096; i += TB) sh[i] = 0;
    __syncthreads();

    const int tmode = g_tmode;
    const longlong2* t64 = (const longlong2*)tgt_raw;
    const int4*      t32 = (const int4*)tgt_raw;

    int stride = GRID_A * TB;
    int q0 = blockIdx.x * TB + threadIdx.x;
    #pragma unroll
    for (int it = 0; it < 2; it++) {
        int q = q0 + it * stride;
        int p  = q << 2;
        int n  = p >> 19;
        int hw = p & (HW_ - 1);
        const float4* base = (const float4*)(logits + (size_t)n * (NCLS * (size_t)HW_) + hw);
        int t0, t1, t2, t3;
        if (tmode) {
            longlong2 ta = __ldg(t64 + 2 * q);
            longlong2 tb = __ldg(t64 + 2 * q + 1);
            t0 = (int)ta.x; t1 = (int)ta.y; t2 = (int)tb.x; t3 = (int)tb.y;
        } else {
            int4 tt = __ldg(t32 + q);
            t0 = tt.x; t1 = tt.y; t2 = tt.z; t3 = tt.w;
        }
        float s0 = 0.f, s1 = 0.f, s2 = 0.f, s3 = 0.f;
        float x0 = 0.f, x1 = 0.f, x2 = 0.f, x3 = 0.f;
        #pragma unroll
        for (int c = 0; c < NCLS; c++) {
            float4 v = __ldg(base + (size_t)c * (HW_ / 4));
            s0 += __expf(v.x); s1 += __expf(v.y); s2 += __expf(v.z); s3 += __expf(v.w);
            if (c == t0) x0 = v.x;
            if (c == t1) x1 = v.y;
            if (c == t2) x2 = v.z;
            if (c == t3) x3 = v.w;
        }
        float l0 = __logf(s0) - x0, l1 = __logf(s1) - x1;
        float l2 = __logf(s2) - x2, l3 = __logf(s3) - x3;
        ((float4*)g_loss)[q] = make_float4(l0, l1, l2, l3);
        if (l0 > 0.f) atomicAdd(&sh[__float_as_uint(l0) >> 20], 1u);
        if (l1 > 0.f) atomicAdd(&sh[__float_as_uint(l1) >> 20], 1u);
        if (l2 > 0.f) atomicAdd(&sh[__float_as_uint(l2) >> 20], 1u);
        if (l3 > 0.f) atomicAdd(&sh[__float_as_uint(l3) >> 20], 1u);
    }
    __syncthreads();
    for (int i = threadIdx.x; i < 4096; i += TB) {
        unsigned c = sh[i];
        if (c) atomicAdd(&g_hist0[i], c);
    }
}

// ------------------------------------------------------------------
// Descending scan over a 4096-bin histogram. Result goes to SHARED
// (*out_bin, *out_r); caller publishes from t0. 256 threads, 16 bins each.
__device__ void scan4096(const unsigned* __restrict__ hist, unsigned k,
                         unsigned* ss, unsigned* out_bin, unsigned* out_r,
                         bool derive_k) {
    int t = threadIdx.x;
    unsigned cnt[16]; unsigned myv = 0;
    #pragma unroll
    for (int i = 0; i < 16; i++) { cnt[i] = __ldcg(&hist[4095 - (t * 16 + i)]); myv += cnt[i]; }
    ss[t] = myv; __syncthreads();
    for (int off = 1; off < 256; off <<= 1) {
        unsigned x = (t >= off) ? ss[t - off] : 0u;
        __syncthreads(); ss[t] += x; __syncthreads();
    }
    if (derive_k) {
        unsigned total = ss[255];          // uniform
        if (total == 0) return;            // *out_bin stays INV
        unsigned nk = (unsigned)(0.7f * (float)total);
        if (nk < 100000u) nk = 100000u;
        if (nk > total)   nk = total;
        k = nk;
    }
    unsigned hi = ss[t], lo = hi - myv;
    if (k > lo && k <= hi) {               // exactly one thread wins
        unsigned cum = lo;
        #pragma unroll
        for (int i = 0; i < 16; i++) {
            cum += cnt[i];
            if (k <= cum) {
                *out_bin = 4095u - (t * 16 + i);
                *out_r   = k - (cum - cnt[i]);
                break;
            }
        }
    }
}

// ------------------------------------------------------------------
// Persistent select kernel: loads losses into registers ONCE, then
// scan0 -> hist1 -> scan1 -> byte phase -> final, with spin grid barriers.
__global__ void __launch_bounds__(TB, 4) k_select(float* __restrict__ out) {
    __shared__ unsigned sh[4096];       // hist1 staging / (cnt2, fsum2 in phase C)
    __shared__ unsigned s_ss[256];      // scan workspace
    __shared__ double   s_rd[256];
    __shared__ unsigned s_rc[256];
    __shared__ unsigned s_bin, s_r;
    __shared__ bool     s_last;

    int t = threadIdx.x;
    for (int i = t; i < 4096; i += TB) sh[i] = 0;
    if (t == 0) { s_bin = INV; s_r = 0; }

    // ---- load this thread's loss values into registers ----
    const uint4* lossv = (const uint4*)g_loss;
    uint4 v[VPT];
    bool  ok[VPT];
    int stride = GRID_B * TB;
    int q0 = blockIdx.x * TB + t;
    #pragma unroll
    for (int i = 0; i < VPT; i++) {
        int q = q0 + i * stride;
        ok[i] = (q < NPIX4);
        v[i] = ok[i] ? __ldg(lossv + q) : make_uint4(0, 0, 0, 0);
    }
    __syncthreads();

    // ---- scan0 (block 0) while other blocks' loads are in flight ----
    if (blockIdx.x == 0) {
        scan4096(g_hist0, 0, s_ss, &s_bin, &s_r, true);
        __syncthreads();                       // winner's shared write visible
        if (t == 0) {
            if (s_bin != INV) { g_prefix0 = s_bin; g_k1 = s_r; }
            __threadfence();
            atomicExch(&g_flag0, 1u);
        }
    }
    if (t == 0) { while (*(volatile unsigned*)&g_flag0 == 0u) __nanosleep(64); }
    __syncthreads();
    __threadfence();
    unsigned pref0 = *(volatile unsigned*)&g_prefix0;

    // ---- hist1 from registers ----
    if (pref0 != INV) {
        #pragma unroll
        for (int i = 0; i < VPT; i++) {
            if (!ok[i]) continue;
            unsigned b;
            b = v[i].x; if ((int)b > 0 && (b >> 20) == pref0) atomicAdd(&sh[(b >> 8) & 0xFFFu], 1u);
            b = v[i].y; if ((int)b > 0 && (b >> 20) == pref0) atomicAdd(&sh[(b >> 8) & 0xFFFu], 1u);
            b = v[i].z; if ((int)b > 0 && (b >> 20) == pref0) atomicAdd(&sh[(b >> 8) & 0xFFFu], 1u);
            b = v[i].w; if ((int)b > 0 && (b >> 20) == pref0) atomicAdd(&sh[(b >> 8) & 0xFFFu], 1u);
        }
        __syncthreads();
        for (int i = t; i < 4096; i += TB) {
            unsigned c = sh[i];
            if (c) atomicAdd(&g_hist1[i], c);
        }
    }
    __threadfence();
    __syncthreads();        // ALL threads' hist1 atomics issued before done++
    if (t == 0) s_last = (atomicAdd(&g_done1, 1u) == GRID_B - 1);
    __syncthreads();

    // ---- scan1 (last-arriving block) ----
    if (s_last) {
        if (t == 0) { s_bin = INV; s_r = 0; }
        __syncthreads();
        if (pref0 != INV) {
            scan4096(g_hist1, __ldcg(&g_k1), s_ss, &s_bin, &s_r, false);
            __syncthreads();
        }
        if (t == 0) {
            if (pref0 != INV && s_bin != INV) {
                g_prefix01 = (pref0 << 12) | s_bin;
                g_k2 = s_r;
            }
            __threadfence();
            atomicExch(&g_flag1, 1u);
        }
    }
    if (t == 0) { while (*(volatile unsigned*)&g_flag1 == 0u) __nanosleep(64); }
    __syncthreads();
    __threadfence();
    unsigned pref01 = *(volatile unsigned*)&g_prefix01;

    // ---- byte-level phase from registers ----
    unsigned* s_cnt2 = sh;                    // [0..255]
    float*    s_fs2  = (float*)(sh + 256);    // [256..511]
    for (int i = t; i < 256; i += TB) { s_cnt2[i] = 0; s_fs2[i] = 0.f; }
    __syncthreads();

    float    fHi = 0.f;                       // <=16 exact float adds per thread
    unsigned cHi = 0;
    if (pref01 != INV) {
        #pragma unroll
        for (int i = 0; i < VPT; i++) {
            if (!ok[i]) continue;
            #pragma unroll
            for (int j = 0; j < 4; j++) {
                unsigned bb = (j == 0) ? v[i].x : (j == 1) ? v[i].y : (j == 2) ? v[i].z : v[i].w;
                if ((int)bb > 0) {
                    unsigned p24 = bb >> 8;
                    if (p24 > pref01) { fHi += __uint_as_float(bb); cHi++; }
                    else if (p24 == pref01) {
                        atomicAdd(&s_cnt2[bb & 0xFFu], 1u);
                        atomicAdd(&s_fs2[bb & 0xFFu], __uint_as_float(bb));
                    }
                }
            }
        }
    } else {
        // no valid pixels: plain mean over everything
        #pragma unroll
        for (int i = 0; i < VPT; i++) {
            if (!ok[i]) continue;
            fHi += __uint_as_float(v[i].x) + __uint_as_float(v[i].y)
                 + __uint_as_float(v[i].z) + __uint_as_float(v[i].w);
        }
    }

    s_rd[t] = (double)fHi; s_rc[t] = cHi;
    __syncthreads();
    for (int off = 128; off > 0; off >>= 1) {
        if (t < off) { s_rd[t] += s_rd[t + off]; s_rc[t] += s_rc[t + off]; }
        __syncthreads();
    }
    if (t == 0) {
        atomicAdd(&g_sumHi, s_rd[0]);
        if (s_rc[0]) atomicAdd(&g_cntHi, s_rc[0]);
    }
    for (int i = t; i < 256; i += TB) {
        if (s_cnt2[i]) { atomicAdd(&g_cnt2[i], s_cnt2[i]); atomicAdd(&g_sum2[i], s_fs2[i]); }
    }
    __threadfence();
    __syncthreads();        // all byte-phase atomics issued before done++
    if (t == 0) s_last = (atomicAdd(&g_done2, 1u) == GRID_B - 1);
    __syncthreads();
    if (!s_last) return;

    if (t == 0) {
        double outv;
        if (pref01 == INV) {
            outv = __ldcg(&g_sumHi) / (double)NPIX;
        } else {
            unsigned k2 = __ldcg(&g_k2);
            unsigned cum = 0;
            double ssum = 0.0;
            for (int b = 255; b >= 0; b--) {
                unsigned c = __ldcg(&g_cnt2[b]);
                ssum += (double)__ldcg(&g_sum2[b]);
                cum  += c;
                if (cum >= k2) break;            // threshold byte reached (ties kept)
            }
            double   ktot = __ldcg(&g_sumHi) + ssum;
            unsigned kcnt = __ldcg(&g_cntHi) + cum;
            if (kcnt == 0) kcnt = 1;
            outv = ktot / (double)kcnt;
        }
        out[0] = (float)outv;
    }
}

// ------------------------------------------------------------------
extern "C" void kernel_launch(void* const* d_in, const int* in_sizes, int n_in,
                              void* d_out, int out_size) {
    const float* logits = (const float*)d_in[0];
    const void*  tgt    = d_in[1];
    float* out = (float*)d_out;

    k_init   <<<16, 256>>>(tgt);
    k_loss   <<<GRID_A, TB>>>(logits, tgt);
    k_select <<<GRID_B, TB>>>(out);
}

// round 6
// speedup vs baseline: 1.7701x; 1.0791x over previous
#include <cuda_runtime.h>

#define NCLS 19
#define HW_   (512*1024)        // 2^19
#define NPIX  (4*HW_)           // 2,097,152
#define NPIX4 (NPIX/4)
#define GRIDP 592               // 4 CTAs/SM * 148 SMs -> co-resident
#define TB    256
#define VPT   4                 // quads per thread: 592*256*4 >= NPIX4
#define INV   0xFFFFFFFFu

// ---- static scratch (zero-initialized at load; self-cleaned each call) ----
__device__ unsigned g_hist0[4096];
__device__ unsigned g_hist1[4096];
__device__ unsigned g_cnt2[256];
__device__ float    g_sum2[256];
__device__ double   g_sumHi;
__device__ unsigned g_cntHi;
__device__ unsigned g_pref0p1, g_pref01p1, g_k1, g_k2;   // prefix+1; 0 = invalid
__device__ unsigned g_done0, g_done1, g_done2, g_flag0, g_flag1;

// ------------------------------------------------------------------
// Descending scan over a 4096-bin histogram; winning thread writes the
// (bin, rank) into shared outputs. 256 threads, 16 bins each.
__device__ void scan4096(const unsigned* __restrict__ hist, unsigned k,
                         unsigned* ss, unsigned* out_bin, unsigned* out_r,
                         bool derive_k) {
    int t = threadIdx.x;
    unsigned cnt[16]; unsigned myv = 0;
    #pragma unroll
    for (int i = 0; i < 16; i++) { cnt[i] = __ldcg(&hist[4095 - (t * 16 + i)]); myv += cnt[i]; }
    ss[t] = myv; __syncthreads();
    for (int off = 1; off < 256; off <<= 1) {
        unsigned x = (t >= off) ? ss[t - off] : 0u;
        __syncthreads(); ss[t] += x; __syncthreads();
    }
    if (derive_k) {
        unsigned total = ss[255];          // uniform
        if (total == 0) return;            // *out_bin stays INV
        unsigned nk = (unsigned)(0.7f * (float)total);
        if (nk < 100000u) nk = 100000u;
        if (nk > total)   nk = total;
        k = nk;
    }
    unsigned hi = ss[t], lo = hi - myv;
    if (k > lo && k <= hi) {               // exactly one thread wins
        unsigned cum = lo;
        #pragma unroll
        for (int i = 0; i < 16; i++) {
            cum += cnt[i];
            if (k <= cum) {
                *out_bin = 4095u - (t * 16 + i);
                *out_r   = k - (cum - cnt[i]);
                break;
            }
        }
    }
}

// ------------------------------------------------------------------
// Single persistent kernel: NLL in registers -> hist0 -> scan0 -> hist1 ->
// scan1 -> byte phase -> final mean -> self-clean. Spin grid barriers.
__global__ void __launch_bounds__(TB, 4) k_ohem(const float* __restrict__ logits,
                                                const void* __restrict__ tgt_raw,
                                                float* __restrict__ out) {
    __shared__ unsigned sh[4096];       // hist staging / byte-phase cnt+sum
    __shared__ unsigned s_ss[256];
    __shared__ double   s_rd[256];
    __shared__ unsigned s_rc[256];
    __shared__ unsigned s_bin, s_r;
    __shared__ bool     s_last;

    int t = threadIdx.x;
    for (int i = t; i < 4096; i += TB) sh[i] = 0;
    __syncthreads();

    // ---- dtype detection (uniform; 8 cached loads) ----
    const long long* tdet = (const long long*)tgt_raw;
    int tmode = 1;
    #pragma unroll
    for (int i = 0; i < 8; i++) {
        long long x = tdet[i];
        if (x < 0 || x >= (long long)NCLS) tmode = 0;
    }
    const longlong2* t64 = (const longlong2*)tgt_raw;
    const int4*      t32 = (const int4*)tgt_raw;

    // ---- Phase A: compute losses into registers + shared hist0 ----
    uint4 v[VPT];
    bool  ok[VPT];
    int stride = GRIDP * TB;
    int q0 = blockIdx.x * TB + t;
    #pragma unroll
    for (int i = 0; i < VPT; i++) {
        int q = q0 + i * stride;
        ok[i] = (q < NPIX4);
        if (ok[i]) {
            int p  = q << 2;
            int n  = p >> 19;
            int hw = p & (HW_ - 1);
            const float4* base = (const float4*)(logits + (size_t)n * (NCLS * (size_t)HW_) + hw);
            int t0, t1, t2, t3;
            if (tmode) {
                longlong2 ta = __ldg(t64 + 2 * q);
                longlong2 tb = __ldg(t64 + 2 * q + 1);
                t0 = (int)ta.x; t1 = (int)ta.y; t2 = (int)tb.x; t3 = (int)tb.y;
            } else {
                int4 tt = __ldg(t32 + q);
                t0 = tt.x; t1 = tt.y; t2 = tt.z; t3 = tt.w;
            }
            float s0 = 0.f, s1 = 0.f, s2 = 0.f, s3 = 0.f;
            float x0 = 0.f, x1 = 0.f, x2 = 0.f, x3 = 0.f;
            #pragma unroll
            for (int c = 0; c < NCLS; c++) {
                float4 w = __ldg(base + (size_t)c * (HW_ / 4));
                s0 += __expf(w.x); s1 += __expf(w.y); s2 += __expf(w.z); s3 += __expf(w.w);
                if (c == t0) x0 = w.x;
                if (c == t1) x1 = w.y;
                if (c == t2) x2 = w.z;
                if (c == t3) x3 = w.w;
            }
            float l0 = __logf(s0) - x0, l1 = __logf(s1) - x1;
            float l2 = __logf(s2) - x2, l3 = __logf(s3) - x3;
            v[i] = make_uint4(__float_as_uint(l0), __float_as_uint(l1),
                              __float_as_uint(l2), __float_as_uint(l3));
            if (l0 > 0.f) atomicAdd(&sh[v[i].x >> 20], 1u);
            if (l1 > 0.f) atomicAdd(&sh[v[i].y >> 20], 1u);
            if (l2 > 0.f) atomicAdd(&sh[v[i].z >> 20], 1u);
            if (l3 > 0.f) atomicAdd(&sh[v[i].w >> 20], 1u);
        } else {
            v[i] = make_uint4(0, 0, 0, 0);
        }
    }
    __syncthreads();
    for (int i = t; i < 4096; i += TB) {
        unsigned c = sh[i];
        if (c) atomicAdd(&g_hist0[i], c);
    }
    __threadfence();
    __syncthreads();                       // all hist0 atomics issued
    if (t == 0) s_last = (atomicAdd(&g_done0, 1u) == GRIDP - 1);
    __syncthreads();

    // re-zero sh for hist1 while waiting
    for (int i = t; i < 4096; i += TB) sh[i] = 0;

    // ---- scan0 by last-arriving block ----
    if (s_last) {
        if (t == 0) { s_bin = INV; s_r = 0; }
        __syncthreads();
        scan4096(g_hist0, 0, s_ss, &s_bin, &s_r, true);
        __syncthreads();
        if (t == 0) {
            if (s_bin != INV) { g_pref0p1 = s_bin + 1u; g_k1 = s_r; }
            __threadfence();
            atomicExch(&g_flag0, 1u);
        }
    }
    if (t == 0) { while (*(volatile unsigned*)&g_flag0 == 0u) __nanosleep(64); }
    __syncthreads();
    __threadfence();
    unsigned p0p1 = *(volatile unsigned*)&g_pref0p1;

    // ---- hist1 from registers ----
    if (p0p1 != 0u) {
        unsigned pref0 = p0p1 - 1u;
        #pragma unroll
        for (int i = 0; i < VPT; i++) {
            if (!ok[i]) continue;
            unsigned b;
            b = v[i].x; if ((int)b > 0 && (b >> 20) == pref0) atomicAdd(&sh[(b >> 8) & 0xFFFu], 1u);
            b = v[i].y; if ((int)b > 0 && (b >> 20) == pref0) atomicAdd(&sh[(b >> 8) & 0xFFFu], 1u);
            b = v[i].z; if ((int)b > 0 && (b >> 20) == pref0) atomicAdd(&sh[(b >> 8) & 0xFFFu], 1u);
            b = v[i].w; if ((int)b > 0 && (b >> 20) == pref0) atomicAdd(&sh[(b >> 8) & 0xFFFu], 1u);
        }
        __syncthreads();
        for (int i = t; i < 4096; i += TB) {
            unsigned c = sh[i];
            if (c) atomicAdd(&g_hist1[i], c);
        }
    }
    __threadfence();
    __syncthreads();                       // all hist1 atomics issued
    if (t == 0) s_last = (atomicAdd(&g_done1, 1u) == GRIDP - 1);
    __syncthreads();

    // ---- scan1 by last-arriving block ----
    if (s_last) {
        if (t == 0) { s_bin = INV; s_r = 0; }
        __syncthreads();
        if (p0p1 != 0u) {
            scan4096(g_hist1, __ldcg(&g_k1), s_ss, &s_bin, &s_r, false);
            __syncthreads();
        }
        if (t == 0) {
            if (p0p1 != 0u && s_bin != INV) {
                g_pref01p1 = ((((p0p1 - 1u) << 12) | s_bin)) + 1u;
                g_k2 = s_r;
            }
            __threadfence();
            atomicExch(&g_flag1, 1u);
        }
    }
    if (t == 0) { while (*(volatile unsigned*)&g_flag1 == 0u) __nanosleep(64); }
    __syncthreads();
    __threadfence();
    unsigned p01p1 = *(volatile unsigned*)&g_pref01p1;

    // ---- byte-level phase from registers ----
    unsigned* s_cnt2 = sh;                    // [0..255]
    float*    s_fs2  = (float*)(sh + 256);    // [256..511]
    for (int i = t; i < 256; i += TB) { s_cnt2[i] = 0; s_fs2[i] = 0.f; }
    __syncthreads();

    float    fHi = 0.f;                       // <=16 exact float adds
    unsigned cHi = 0;
    if (p01p1 != 0u) {
        unsigned pref01 = p01p1 - 1u;
        #pragma unroll
        for (int i = 0; i < VPT; i++) {
            if (!ok[i]) continue;
            #pragma unroll
            for (int j = 0; j < 4; j++) {
                unsigned bb = (j == 0) ? v[i].x : (j == 1) ? v[i].y : (j == 2) ? v[i].z : v[i].w;
                if ((int)bb > 0) {
                    unsigned p24 = bb >> 8;
                    if (p24 > pref01) { fHi += __uint_as_float(bb); cHi++; }
                    else if (p24 == pref01) {
                        atomicAdd(&s_cnt2[bb & 0xFFu], 1u);
                        atomicAdd(&s_fs2[bb & 0xFFu], __uint_as_float(bb));
                    }
                }
            }
        }
    } else {
        // no valid pixels: plain mean over everything
        #pragma unroll
        for (int i = 0; i < VPT; i++) {
            if (!ok[i]) continue;
            fHi += __uint_as_float(v[i].x) + __uint_as_float(v[i].y)
                 + __uint_as_float(v[i].z) + __uint_as_float(v[i].w);
        }
    }

    s_rd[t] = (double)fHi; s_rc[t] = cHi;
    __syncthreads();
    for (int off = 128; off > 0; off >>= 1) {
        if (t < off) { s_rd[t] += s_rd[t + off]; s_rc[t] += s_rc[t + off]; }
        __syncthreads();
    }
    if (t == 0) {
        atomicAdd(&g_sumHi, s_rd[0]);
        if (s_rc[0]) atomicAdd(&g_cntHi, s_rc[0]);
    }
    for (int i = t; i < 256; i += TB) {
        if (s_cnt2[i]) { atomicAdd(&g_cnt2[i], s_cnt2[i]); atomicAdd(&g_sum2[i], s_fs2[i]); }
    }
    __threadfence();
    __syncthreads();                       // all byte-phase atomics issued
    if (t == 0) s_last = (atomicAdd(&g_done2, 1u) == GRIDP - 1);
    __syncthreads();
    if (!s_last) return;

    // ---- final mean (last block only) ----
    if (t == 0) {
        double outv;
        if (p01p1 == 0u) {
            outv = __ldcg(&g_sumHi) / (double)NPIX;
        } else {
            unsigned k2 = __ldcg(&g_k2);
            unsigned cum = 0;
            double ssum = 0.0;
            for (int b = 255; b >= 0; b--) {
                unsigned c = __ldcg(&g_cnt2[b]);
                ssum += (double)__ldcg(&g_sum2[b]);
                cum  += c;
                if (cum >= k2) break;            // threshold byte reached (ties kept)
            }
            double   ktot = __ldcg(&g_sumHi) + ssum;
            unsigned kcnt = __ldcg(&g_cntHi) + cum;
            if (kcnt == 0) kcnt = 1;
            outv = ktot / (double)kcnt;
        }
        out[0] = (float)outv;
    }
    __syncthreads();

    // ---- self-clean for next graph replay (all other blocks have exited
    //      past every flag/counter read) ----
    for (int i = t; i < 4096; i += TB) { g_hist0[i] = 0; g_hist1[i] = 0; }
    for (int i = t; i < 256;  i += TB) { g_cnt2[i] = 0; g_sum2[i] = 0.f; }
    if (t == 0) {
        g_sumHi = 0.0; g_cntHi = 0;
        g_pref0p1 = 0; g_pref01p1 = 0; g_k1 = 0; g_k2 = 0;
        g_done0 = 0; g_done1 = 0; g_done2 = 0;
        g_flag0 = 0; g_flag1 = 0;
        __threadfence();
    }
}

// ------------------------------------------------------------------
extern "C" void kernel_launch(void* const* d_in, const int* in_sizes, int n_in,
                              void* d_out, int out_size) {
    const float* logits = (const float*)d_in[0];
    const void*  tgt    = d_in[1];
    float* out = (float*)d_out;

    k_ohem<<<GRIDP, TB>>>(logits, tgt, out);
}